// round 2
// baseline (speedup 1.0000x reference)
#include <cuda_runtime.h>
#include <cuda_bf16.h>
#include <cstdint>

// EnhancedMoEModel: out[b] = sum_e probs[b,e] * sigmoid( relu( relu(x W1e + b1e) W2e + b2e ) W3e + b3e )
// B=524288, D=32, H=64, H2=32, E=8, O=1.
//
// R1 change: 64 rows per warp-tile (4 x 16-row subtiles). Each B-fragment LDS is
// reused by 4 mmas -> 4x less shared-memory traffic (R0 bottleneck: L1 at 72%).
// Bias folded into accumulator init. Layer-1 C fragments repack directly into
// layer-2 A fragments (no memory round trip).

#define NUM_E 8
#define SMEM_BYTES (4096*8 + 4096*8 + (256+512+256+8)*4)

__device__ __forceinline__ uint32_t packbf(float lo, float hi) {
    __nv_bfloat162 h = __floats2bfloat162_rn(lo, hi);
    return *reinterpret_cast<uint32_t*>(&h);
}

__device__ __forceinline__ void mma16816(float d[4], const uint32_t a[4], uint32_t b0, uint32_t b1) {
    asm volatile(
        "mma.sync.aligned.m16n8k16.row.col.f32.bf16.bf16.f32 "
        "{%0,%1,%2,%3}, {%4,%5,%6,%7}, {%8,%9}, {%0,%1,%2,%3};\n"
        : "+f"(d[0]), "+f"(d[1]), "+f"(d[2]), "+f"(d[3])
        : "r"(a[0]), "r"(a[1]), "r"(a[2]), "r"(a[3]), "r"(b0), "r"(b1));
}

__global__ void __launch_bounds__(128)
moe_kernel(const float* __restrict__ x,
           const float* __restrict__ probs,
           const float* __restrict__ W1, const float* __restrict__ b1,
           const float* __restrict__ W2, const float* __restrict__ b2,
           const float* __restrict__ W3, const float* __restrict__ b3,
           float* __restrict__ out, int NT64)
{
    extern __shared__ unsigned char smem_raw[];
    uint2* sW1 = reinterpret_cast<uint2*>(smem_raw);            // 4096 entries (32 KB)
    uint2* sW2 = sW1 + 4096;                                    // 4096 entries (32 KB)
    float* sW3 = reinterpret_cast<float*>(sW2 + 4096);          // 256
    float* sB1 = sW3 + 256;                                     // 512
    float* sB2 = sB1 + 512;                                     // 256
    float* sB3 = sB2 + 256;                                     // 8

    // ---- one-time weight pre-swizzle into mma B-fragment order (bf16x2 pairs) ----
    // B fragment (m16n8k16, col): lane t: b0={B[2c][n],B[2c+1][n]}, b1={B[2c+8][n],B[2c+9][n]},
    // c=t%4, n=t/4.
    for (int idx = threadIdx.x; idx < 4096; idx += blockDim.x) {
        int lanei = idx & 31, j = (idx >> 5) & 7, s = (idx >> 8) & 1, e = idx >> 9;
        int cc = lanei & 3, nn = lanei >> 2;
        int k0 = 16 * s + 2 * cc, col = 8 * j + nn;
        const float* base = W1 + (size_t)e * 32 * 64;
        float v00 = base[(k0    ) * 64 + col];
        float v01 = base[(k0 + 1) * 64 + col];
        float v10 = base[(k0 + 8) * 64 + col];
        float v11 = base[(k0 + 9) * 64 + col];
        sW1[idx] = make_uint2(packbf(v00, v01), packbf(v10, v11));
    }
    for (int idx = threadIdx.x; idx < 4096; idx += blockDim.x) {
        int lanei = idx & 31, j = (idx >> 5) & 3, s = (idx >> 7) & 3, e = idx >> 9;
        int cc = lanei & 3, nn = lanei >> 2;
        int k0 = 16 * s + 2 * cc, col = 8 * j + nn;
        const float* base = W2 + (size_t)e * 64 * 32;
        float v00 = base[(k0    ) * 32 + col];
        float v01 = base[(k0 + 1) * 32 + col];
        float v10 = base[(k0 + 8) * 32 + col];
        float v11 = base[(k0 + 9) * 32 + col];
        sW2[idx] = make_uint2(packbf(v00, v01), packbf(v10, v11));
    }
    for (int idx = threadIdx.x; idx < 256; idx += blockDim.x) sW3[idx] = W3[idx];
    for (int idx = threadIdx.x; idx < 512; idx += blockDim.x) sB1[idx] = b1[idx];
    for (int idx = threadIdx.x; idx < 256; idx += blockDim.x) sB2[idx] = b2[idx];
    if (threadIdx.x < 8) sB3[threadIdx.x] = b3[threadIdx.x];
    __syncthreads();

    const int lane = threadIdx.x & 31;
    const int c = lane & 3;       // quad column index
    const int rq = lane >> 2;     // row within 8-row group
    const int warp_global = blockIdx.x * 4 + (threadIdx.x >> 5);
    const int nwarps = gridDim.x * 4;

    for (int tile = warp_global; tile < NT64; tile += nwarps) {
        const int rowbase = tile << 6;

        // ---- load x A-fragments for 4 subtiles (f32 -> bf16x2 on the fly) ----
        uint32_t xa[4][2][4];
        #pragma unroll
        for (int r = 0; r < 4; r++) {
            const float* xr0 = x + (size_t)(rowbase + r * 16 + rq) * 32;
            const float* xr1 = xr0 + 8 * 32;
            #pragma unroll
            for (int s = 0; s < 2; s++) {
                const int col = 16 * s + 2 * c;
                float2 v00 = *reinterpret_cast<const float2*>(xr0 + col);
                float2 v10 = *reinterpret_cast<const float2*>(xr1 + col);
                float2 v01 = *reinterpret_cast<const float2*>(xr0 + col + 8);
                float2 v11 = *reinterpret_cast<const float2*>(xr1 + col + 8);
                xa[r][s][0] = packbf(v00.x, v00.y);
                xa[r][s][1] = packbf(v10.x, v10.y);
                xa[r][s][2] = packbf(v01.x, v01.y);
                xa[r][s][3] = packbf(v11.x, v11.y);
            }
        }

        float oa[4][2];
        #pragma unroll
        for (int r = 0; r < 4; r++) { oa[r][0] = 0.f; oa[r][1] = 0.f; }

        #pragma unroll 1
        for (int e = 0; e < NUM_E; e++) {
            // ---- layer 1: [64,32] @ [32,64], B-frag loaded once per (s,j), used 4x ----
            uint32_t ha[4][4][4];
            const uint2* w1e = sW1 + e * 512 + lane;
            #pragma unroll
            for (int j = 0; j < 8; j++) {
                uint2 B0 = w1e[j * 32];            // s = 0
                uint2 B1 = w1e[(8 + j) * 32];      // s = 1
                float2 bb = *reinterpret_cast<const float2*>(sB1 + e * 64 + 8 * j + 2 * c);
                const int s2 = j >> 1, h = j & 1;
                #pragma unroll
                for (int r = 0; r < 4; r++) {
                    float a[4] = {bb.x, bb.y, bb.x, bb.y};   // bias folded into acc init
                    mma16816(a, xa[r][0], B0.x, B0.y);
                    mma16816(a, xa[r][1], B1.x, B1.y);
                    ha[r][s2][h * 2 + 0] = packbf(fmaxf(a[0], 0.f), fmaxf(a[1], 0.f));
                    ha[r][s2][h * 2 + 1] = packbf(fmaxf(a[2], 0.f), fmaxf(a[3], 0.f));
                }
            }

            // ---- layer 2: [64,64] @ [64,32], B-frags loaded once per j2, used 4x ----
            float p[4][2];
            #pragma unroll
            for (int r = 0; r < 4; r++) { p[r][0] = 0.f; p[r][1] = 0.f; }
            const uint2* w2e = sW2 + e * 512 + lane;
            #pragma unroll
            for (int j2 = 0; j2 < 4; j2++) {
                uint2 C0 = w2e[(0 * 4 + j2) * 32];
                uint2 C1 = w2e[(1 * 4 + j2) * 32];
                uint2 C2 = w2e[(2 * 4 + j2) * 32];
                uint2 C3 = w2e[(3 * 4 + j2) * 32];
                float2 w   = *reinterpret_cast<const float2*>(sW3 + e * 32 + 8 * j2 + 2 * c);
                float2 bb2 = *reinterpret_cast<const float2*>(sB2 + e * 32 + 8 * j2 + 2 * c);
                #pragma unroll
                for (int r = 0; r < 4; r++) {
                    float a2[4] = {bb2.x, bb2.y, bb2.x, bb2.y};
                    mma16816(a2, ha[r][0], C0.x, C0.y);
                    mma16816(a2, ha[r][1], C1.x, C1.y);
                    mma16816(a2, ha[r][2], C2.x, C2.y);
                    mma16816(a2, ha[r][3], C3.x, C3.y);
                    p[r][0] += fmaxf(a2[0], 0.f) * w.x + fmaxf(a2[1], 0.f) * w.y;
                    p[r][1] += fmaxf(a2[2], 0.f) * w.x + fmaxf(a2[3], 0.f) * w.y;
                }
            }

            // ---- layer 3: quad reduce + sigmoid + prob-weighted accumulate ----
            #pragma unroll
            for (int r = 0; r < 4; r++) {
                p[r][0] += __shfl_xor_sync(0xffffffffu, p[r][0], 1);
                p[r][0] += __shfl_xor_sync(0xffffffffu, p[r][0], 2);
                p[r][1] += __shfl_xor_sync(0xffffffffu, p[r][1], 1);
                p[r][1] += __shfl_xor_sync(0xffffffffu, p[r][1], 2);
            }
            float b3e = sB3[e];
            if (c == 0) {
                #pragma unroll
                for (int r = 0; r < 4; r++) {
                    float z0 = p[r][0] + b3e;
                    float z1 = p[r][1] + b3e;
                    float s0 = 1.f / (1.f + __expf(-z0));
                    float s1 = 1.f / (1.f + __expf(-z1));
                    oa[r][0] += s0 * probs[(size_t)(rowbase + r * 16 + rq) * NUM_E + e];
                    oa[r][1] += s1 * probs[(size_t)(rowbase + r * 16 + 8 + rq) * NUM_E + e];
                }
            }
        }

        if (c == 0) {
            #pragma unroll
            for (int r = 0; r < 4; r++) {
                out[rowbase + r * 16 + rq]     = oa[r][0];
                out[rowbase + r * 16 + 8 + rq] = oa[r][1];
            }
        }
    }
}

extern "C" void kernel_launch(void* const* d_in, const int* in_sizes, int n_in,
                              void* d_out, int out_size) {
    const float* x     = (const float*)d_in[0];
    const float* probs = (const float*)d_in[1];
    const float* W1    = (const float*)d_in[2];
    const float* b1    = (const float*)d_in[3];
    const float* W2    = (const float*)d_in[4];
    const float* b2    = (const float*)d_in[5];
    const float* W3    = (const float*)d_in[6];
    const float* b3    = (const float*)d_in[7];
    float* out = (float*)d_out;

    const int B    = in_sizes[0] / 32;
    const int NT64 = B / 64;   // 8192 warp-tiles of 64 rows

    cudaFuncSetAttribute(moe_kernel, cudaFuncAttributeMaxDynamicSharedMemorySize, SMEM_BYTES);

    // 512 CTAs x 4 warps = 2048 warps -> exactly 4 tiles per warp (perfect balance)
    moe_kernel<<<512, 128, SMEM_BYTES>>>(x, probs, W1, b1, W2, b2, W3, b3, out, NT64);
}

// round 3
// speedup vs baseline: 1.2640x; 1.2640x over previous
#include <cuda_runtime.h>
#include <cuda_bf16.h>
#include <cstdint>

// EnhancedMoEModel: out[b] = sum_e probs[b,e] * sigmoid( relu( relu(x W1e + b1e) W2e + b2e ) W3e + b3e )
// B=524288, D=32, H=64, H2=32, E=8, O=1.
//
// R2: r=2 (32-row warp tiles) — halves smem B-fragment traffic vs R0 while
// keeping regs ~100 so 2 CTAs x 256 threads co-reside (16 warps/SM, same occ as R0).
// Persistent grid of 296 CTAs (2/SM), weight pre-swizzle paid once per CTA.

#define NUM_E 8
#define SMEM_BYTES (4096*8 + 4096*8 + (256+512+256+8)*4)

__device__ __forceinline__ uint32_t packbf(float lo, float hi) {
    __nv_bfloat162 h = __floats2bfloat162_rn(lo, hi);
    return *reinterpret_cast<uint32_t*>(&h);
}

__device__ __forceinline__ void mma16816(float d[4], const uint32_t a[4], uint32_t b0, uint32_t b1) {
    asm volatile(
        "mma.sync.aligned.m16n8k16.row.col.f32.bf16.bf16.f32 "
        "{%0,%1,%2,%3}, {%4,%5,%6,%7}, {%8,%9}, {%0,%1,%2,%3};\n"
        : "+f"(d[0]), "+f"(d[1]), "+f"(d[2]), "+f"(d[3])
        : "r"(a[0]), "r"(a[1]), "r"(a[2]), "r"(a[3]), "r"(b0), "r"(b1));
}

__global__ void __launch_bounds__(256)
moe_kernel(const float* __restrict__ x,
           const float* __restrict__ probs,
           const float* __restrict__ W1, const float* __restrict__ b1,
           const float* __restrict__ W2, const float* __restrict__ b2,
           const float* __restrict__ W3, const float* __restrict__ b3,
           float* __restrict__ out, int NT32)
{
    extern __shared__ unsigned char smem_raw[];
    uint2* sW1 = reinterpret_cast<uint2*>(smem_raw);            // 4096 entries (32 KB)
    uint2* sW2 = sW1 + 4096;                                    // 4096 entries (32 KB)
    float* sW3 = reinterpret_cast<float*>(sW2 + 4096);          // 256
    float* sB1 = sW3 + 256;                                     // 512
    float* sB2 = sB1 + 512;                                     // 256
    float* sB3 = sB2 + 256;                                     // 8

    // ---- one-time weight pre-swizzle into mma B-fragment order (bf16x2 pairs) ----
    // B fragment (m16n8k16, col): lane t: b0={B[2c][n],B[2c+1][n]}, b1={B[2c+8][n],B[2c+9][n]},
    // c=t%4, n=t/4.
    for (int idx = threadIdx.x; idx < 4096; idx += blockDim.x) {
        int lanei = idx & 31, j = (idx >> 5) & 7, s = (idx >> 8) & 1, e = idx >> 9;
        int cc = lanei & 3, nn = lanei >> 2;
        int k0 = 16 * s + 2 * cc, col = 8 * j + nn;
        const float* base = W1 + (size_t)e * 32 * 64;
        float v00 = base[(k0    ) * 64 + col];
        float v01 = base[(k0 + 1) * 64 + col];
        float v10 = base[(k0 + 8) * 64 + col];
        float v11 = base[(k0 + 9) * 64 + col];
        sW1[idx] = make_uint2(packbf(v00, v01), packbf(v10, v11));
    }
    for (int idx = threadIdx.x; idx < 4096; idx += blockDim.x) {
        int lanei = idx & 31, j = (idx >> 5) & 3, s = (idx >> 7) & 3, e = idx >> 9;
        int cc = lanei & 3, nn = lanei >> 2;
        int k0 = 16 * s + 2 * cc, col = 8 * j + nn;
        const float* base = W2 + (size_t)e * 64 * 32;
        float v00 = base[(k0    ) * 32 + col];
        float v01 = base[(k0 + 1) * 32 + col];
        float v10 = base[(k0 + 8) * 32 + col];
        float v11 = base[(k0 + 9) * 32 + col];
        sW2[idx] = make_uint2(packbf(v00, v01), packbf(v10, v11));
    }
    for (int idx = threadIdx.x; idx < 256; idx += blockDim.x) sW3[idx] = W3[idx];
    for (int idx = threadIdx.x; idx < 512; idx += blockDim.x) sB1[idx] = b1[idx];
    for (int idx = threadIdx.x; idx < 256; idx += blockDim.x) sB2[idx] = b2[idx];
    if (threadIdx.x < 8) sB3[threadIdx.x] = b3[threadIdx.x];
    __syncthreads();

    const int lane = threadIdx.x & 31;
    const int c = lane & 3;       // quad column index
    const int rq = lane >> 2;     // row within 8-row group
    const int warp_global = blockIdx.x * 8 + (threadIdx.x >> 5);
    const int nwarps = gridDim.x * 8;

    for (int tile = warp_global; tile < NT32; tile += nwarps) {
        const int rowbase = tile << 5;

        // ---- load x A-fragments for 2 subtiles (f32 -> bf16x2 on the fly) ----
        uint32_t xa[2][2][4];
        #pragma unroll
        for (int r = 0; r < 2; r++) {
            const float* xr0 = x + (size_t)(rowbase + r * 16 + rq) * 32;
            const float* xr1 = xr0 + 8 * 32;
            #pragma unroll
            for (int s = 0; s < 2; s++) {
                const int col = 16 * s + 2 * c;
                float2 v00 = *reinterpret_cast<const float2*>(xr0 + col);
                float2 v10 = *reinterpret_cast<const float2*>(xr1 + col);
                float2 v01 = *reinterpret_cast<const float2*>(xr0 + col + 8);
                float2 v11 = *reinterpret_cast<const float2*>(xr1 + col + 8);
                xa[r][s][0] = packbf(v00.x, v00.y);
                xa[r][s][1] = packbf(v10.x, v10.y);
                xa[r][s][2] = packbf(v01.x, v01.y);
                xa[r][s][3] = packbf(v11.x, v11.y);
            }
        }

        float oa[2][2];
        oa[0][0] = oa[0][1] = oa[1][0] = oa[1][1] = 0.f;

        #pragma unroll 1
        for (int e = 0; e < NUM_E; e++) {
            // ---- layer 1: [32,32] @ [32,64], B-frag loaded once per (s,j), used 2x ----
            uint32_t ha[2][4][4];
            const uint2* w1e = sW1 + e * 512 + lane;
            #pragma unroll
            for (int j = 0; j < 8; j++) {
                uint2 B0 = w1e[j * 32];            // s = 0
                uint2 B1 = w1e[(8 + j) * 32];      // s = 1
                float2 bb = *reinterpret_cast<const float2*>(sB1 + e * 64 + 8 * j + 2 * c);
                const int s2 = j >> 1, h = j & 1;
                #pragma unroll
                for (int r = 0; r < 2; r++) {
                    float a[4] = {bb.x, bb.y, bb.x, bb.y};   // bias folded into acc init
                    mma16816(a, xa[r][0], B0.x, B0.y);
                    mma16816(a, xa[r][1], B1.x, B1.y);
                    ha[r][s2][h * 2 + 0] = packbf(fmaxf(a[0], 0.f), fmaxf(a[1], 0.f));
                    ha[r][s2][h * 2 + 1] = packbf(fmaxf(a[2], 0.f), fmaxf(a[3], 0.f));
                }
            }

            // ---- layer 2: [32,64] @ [64,32], B-frags loaded once per j2, used 2x ----
            float p[2][2];
            p[0][0] = p[0][1] = p[1][0] = p[1][1] = 0.f;
            const uint2* w2e = sW2 + e * 512 + lane;
            #pragma unroll
            for (int j2 = 0; j2 < 4; j2++) {
                uint2 C0 = w2e[(0 * 4 + j2) * 32];
                uint2 C1 = w2e[(1 * 4 + j2) * 32];
                uint2 C2 = w2e[(2 * 4 + j2) * 32];
                uint2 C3 = w2e[(3 * 4 + j2) * 32];
                float2 w   = *reinterpret_cast<const float2*>(sW3 + e * 32 + 8 * j2 + 2 * c);
                float2 bb2 = *reinterpret_cast<const float2*>(sB2 + e * 32 + 8 * j2 + 2 * c);
                #pragma unroll
                for (int r = 0; r < 2; r++) {
                    float a2[4] = {bb2.x, bb2.y, bb2.x, bb2.y};
                    mma16816(a2, ha[r][0], C0.x, C0.y);
                    mma16816(a2, ha[r][1], C1.x, C1.y);
                    mma16816(a2, ha[r][2], C2.x, C2.y);
                    mma16816(a2, ha[r][3], C3.x, C3.y);
                    p[r][0] += fmaxf(a2[0], 0.f) * w.x + fmaxf(a2[1], 0.f) * w.y;
                    p[r][1] += fmaxf(a2[2], 0.f) * w.x + fmaxf(a2[3], 0.f) * w.y;
                }
            }

            // ---- layer 3: quad reduce + sigmoid + prob-weighted accumulate ----
            #pragma unroll
            for (int r = 0; r < 2; r++) {
                p[r][0] += __shfl_xor_sync(0xffffffffu, p[r][0], 1);
                p[r][0] += __shfl_xor_sync(0xffffffffu, p[r][0], 2);
                p[r][1] += __shfl_xor_sync(0xffffffffu, p[r][1], 1);
                p[r][1] += __shfl_xor_sync(0xffffffffu, p[r][1], 2);
            }
            float b3e = sB3[e];
            if (c == 0) {
                #pragma unroll
                for (int r = 0; r < 2; r++) {
                    float z0 = p[r][0] + b3e;
                    float z1 = p[r][1] + b3e;
                    float s0 = 1.f / (1.f + __expf(-z0));
                    float s1 = 1.f / (1.f + __expf(-z1));
                    oa[r][0] += s0 * probs[(size_t)(rowbase + r * 16 + rq) * NUM_E + e];
                    oa[r][1] += s1 * probs[(size_t)(rowbase + r * 16 + 8 + rq) * NUM_E + e];
                }
            }
        }

        if (c == 0) {
            #pragma unroll
            for (int r = 0; r < 2; r++) {
                out[rowbase + r * 16 + rq]     = oa[r][0];
                out[rowbase + r * 16 + 8 + rq] = oa[r][1];
            }
        }
    }
}

extern "C" void kernel_launch(void* const* d_in, const int* in_sizes, int n_in,
                              void* d_out, int out_size) {
    const float* x     = (const float*)d_in[0];
    const float* probs = (const float*)d_in[1];
    const float* W1    = (const float*)d_in[2];
    const float* b1    = (const float*)d_in[3];
    const float* W2    = (const float*)d_in[4];
    const float* b2    = (const float*)d_in[5];
    const float* W3    = (const float*)d_in[6];
    const float* b3    = (const float*)d_in[7];
    float* out = (float*)d_out;

    const int B    = in_sizes[0] / 32;
    const int NT32 = B / 32;   // 16384 warp-tiles of 32 rows

    cudaFuncSetAttribute(moe_kernel, cudaFuncAttributeMaxDynamicSharedMemorySize, SMEM_BYTES);
    cudaFuncSetAttribute(moe_kernel, cudaFuncAttributePreferredSharedMemoryCarveout, 100);

    // 296 persistent CTAs (2 per SM), 2368 warps striding over 16384 tiles
    moe_kernel<<<296, 256, SMEM_BYTES>>>(x, probs, W1, b1, W2, b2, W3, b3, out, NT32);
}

// round 5
// speedup vs baseline: 1.2880x; 1.0190x over previous
#include <cuda_runtime.h>
#include <cuda_bf16.h>
#include <cstdint>

// EnhancedMoEModel: out[b] = sum_e probs[b,e] * sigmoid( relu( relu(x W1e + b1e) W2e + b2e ) W3e + b3e )
// B=524288, D=32, H=64, H2=32, E=8, O=1.
//
// R3: instruction diet at fixed occupancy (issue-bound at 47%).
//  - B-fragments re-packed into uint4 -> LDS.128 (half the LDS instructions)
//  - layer-1 relu done as bf16x2 hmax2 AFTER packing (identical numerics, fewer ops)
//  - W3/b2 fused into one float4 per (e,j2,c)

#define NUM_E 8
// sW1u4 2048 uint4 + sW2u4 2048 uint4 + sWB2 128 float4 + sB1 512 f + sB3 8 f
#define SMEM_BYTES (2048*16 + 2048*16 + 128*16 + 512*4 + 8*4)

__device__ __forceinline__ uint32_t packbf(float lo, float hi) {
    __nv_bfloat162 h = __floats2bfloat162_rn(lo, hi);
    return *reinterpret_cast<uint32_t*>(&h);
}

// pack two f32 to bf16x2, then relu in bf16 (identical to relu-then-pack)
__device__ __forceinline__ uint32_t packbf_relu(float lo, float hi) {
    __nv_bfloat162 h = __floats2bfloat162_rn(lo, hi);
    __nv_bfloat162 z = __floats2bfloat162_rn(0.f, 0.f);
    h = __hmax2(h, z);
    return *reinterpret_cast<uint32_t*>(&h);
}

__device__ __forceinline__ void mma16816(float d[4], const uint32_t a[4], uint32_t b0, uint32_t b1) {
    asm volatile(
        "mma.sync.aligned.m16n8k16.row.col.f32.bf16.bf16.f32 "
        "{%0,%1,%2,%3}, {%4,%5,%6,%7}, {%8,%9}, {%0,%1,%2,%3};\n"
        : "+f"(d[0]), "+f"(d[1]), "+f"(d[2]), "+f"(d[3])
        : "r"(a[0]), "r"(a[1]), "r"(a[2]), "r"(a[3]), "r"(b0), "r"(b1));
}

__global__ void __launch_bounds__(256)
moe_kernel(const float* __restrict__ x,
           const float* __restrict__ probs,
           const float* __restrict__ W1, const float* __restrict__ b1,
           const float* __restrict__ W2, const float* __restrict__ b2,
           const float* __restrict__ W3, const float* __restrict__ b3,
           float* __restrict__ out, int NT32)
{
    extern __shared__ unsigned char smem_raw[];
    uint4*  sW1 = reinterpret_cast<uint4*>(smem_raw);           // 2048 (32 KB): [e][j][lane] = {B(s0), B(s1)}
    uint4*  sW2 = sW1 + 2048;                                   // 2048 (32 KB): [e][j2][half][lane] = {C(2h), C(2h+1)}
    float4* sWB2 = reinterpret_cast<float4*>(sW2 + 2048);       // 128: [e][j2][c] = {w0,w1,b0,b1}
    float*  sB1 = reinterpret_cast<float*>(sWB2 + 128);         // 512
    float*  sB3 = sB1 + 512;                                    // 8

    // ---- one-time weight pre-swizzle into mma B-fragment order (bf16x2 pairs) ----
    // B fragment (m16n8k16, col): lane t: b0={B[2c][n],B[2c+1][n]}, b1={B[2c+8][n],B[2c+9][n]},
    // c=t%4, n=t/4. k-step s adds 16 to k.
    for (int idx = threadIdx.x; idx < 2048; idx += blockDim.x) {
        int lanei = idx & 31, j = (idx >> 5) & 7, e = idx >> 8;
        int cc = lanei & 3, nn = lanei >> 2;
        int col = 8 * j + nn;
        const float* base = W1 + (size_t)e * 32 * 64;
        uint32_t v[2];
        #pragma unroll
        for (int s = 0; s < 2; s++) {
            int k0 = 16 * s + 2 * cc;
            float v00 = base[(k0    ) * 64 + col];
            float v01 = base[(k0 + 1) * 64 + col];
            float v10 = base[(k0 + 8) * 64 + col];
            float v11 = base[(k0 + 9) * 64 + col];
            v[0] = packbf(v00, v01);
            v[1] = packbf(v10, v11);
            if (s == 0) { sW1[idx].x = v[0]; sW1[idx].y = v[1]; }
            else        { sW1[idx].z = v[0]; sW1[idx].w = v[1]; }
        }
    }
    for (int idx = threadIdx.x; idx < 2048; idx += blockDim.x) {
        int lanei = idx & 31, half = (idx >> 5) & 1, j2 = (idx >> 6) & 3, e = idx >> 8;
        int cc = lanei & 3, nn = lanei >> 2;
        int col = 8 * j2 + nn;
        const float* base = W2 + (size_t)e * 64 * 32;
        uint4 outv;
        #pragma unroll
        for (int t = 0; t < 2; t++) {
            int s2 = 2 * half + t;
            int k0 = 16 * s2 + 2 * cc;
            float v00 = base[(k0    ) * 32 + col];
            float v01 = base[(k0 + 1) * 32 + col];
            float v10 = base[(k0 + 8) * 32 + col];
            float v11 = base[(k0 + 9) * 32 + col];
            if (t == 0) { outv.x = packbf(v00, v01); outv.y = packbf(v10, v11); }
            else        { outv.z = packbf(v00, v01); outv.w = packbf(v10, v11); }
        }
        sW2[idx] = outv;
    }
    for (int idx = threadIdx.x; idx < 128; idx += blockDim.x) {
        int cc = idx & 3, j2 = (idx >> 2) & 3, e = idx >> 4;
        int col = 8 * j2 + 2 * cc;
        sWB2[idx] = make_float4(W3[e * 32 + col], W3[e * 32 + col + 1],
                                b2[e * 32 + col], b2[e * 32 + col + 1]);
    }
    for (int idx = threadIdx.x; idx < 512; idx += blockDim.x) sB1[idx] = b1[idx];
    if (threadIdx.x < 8) sB3[threadIdx.x] = b3[threadIdx.x];
    __syncthreads();

    const int lane = threadIdx.x & 31;
    const int c = lane & 3;       // quad column index
    const int rq = lane >> 2;     // row within 8-row group
    const int warp_global = blockIdx.x * 8 + (threadIdx.x >> 5);
    const int nwarps = gridDim.x * 8;

    for (int tile = warp_global; tile < NT32; tile += nwarps) {
        const int rowbase = tile << 5;

        // ---- load x A-fragments for 2 subtiles (f32 -> bf16x2 on the fly) ----
        uint32_t xa[2][2][4];
        #pragma unroll
        for (int r = 0; r < 2; r++) {
            const float* xr0 = x + (size_t)(rowbase + r * 16 + rq) * 32;
            const float* xr1 = xr0 + 8 * 32;
            #pragma unroll
            for (int s = 0; s < 2; s++) {
                const int col = 16 * s + 2 * c;
                float2 v00 = *reinterpret_cast<const float2*>(xr0 + col);
                float2 v10 = *reinterpret_cast<const float2*>(xr1 + col);
                float2 v01 = *reinterpret_cast<const float2*>(xr0 + col + 8);
                float2 v11 = *reinterpret_cast<const float2*>(xr1 + col + 8);
                xa[r][s][0] = packbf(v00.x, v00.y);
                xa[r][s][1] = packbf(v10.x, v10.y);
                xa[r][s][2] = packbf(v01.x, v01.y);
                xa[r][s][3] = packbf(v11.x, v11.y);
            }
        }

        float oa[2][2];
        oa[0][0] = oa[0][1] = oa[1][0] = oa[1][1] = 0.f;

        #pragma unroll 1
        for (int e = 0; e < NUM_E; e++) {
            // ---- layer 1: [32,32] @ [32,64], one LDS.128 per j covers both k-steps ----
            uint32_t ha[2][4][4];
            const uint4* w1e = sW1 + e * 256 + lane;
            #pragma unroll
            for (int j = 0; j < 8; j++) {
                uint4 B = w1e[j * 32];
                float2 bb = *reinterpret_cast<const float2*>(sB1 + e * 64 + 8 * j + 2 * c);
                const int s2 = j >> 1, h = j & 1;
                #pragma unroll
                for (int r = 0; r < 2; r++) {
                    float a[4] = {bb.x, bb.y, bb.x, bb.y};   // bias folded into acc init
                    mma16816(a, xa[r][0], B.x, B.y);
                    mma16816(a, xa[r][1], B.z, B.w);
                    ha[r][s2][h * 2 + 0] = packbf_relu(a[0], a[1]);
                    ha[r][s2][h * 2 + 1] = packbf_relu(a[2], a[3]);
                }
            }

            // ---- layer 2: [32,64] @ [64,32], two LDS.128 per j2 cover 4 k-steps ----
            float p[2][2];
            p[0][0] = p[0][1] = p[1][0] = p[1][1] = 0.f;
            const uint4* w2e = sW2 + e * 256 + lane;
            #pragma unroll
            for (int j2 = 0; j2 < 4; j2++) {
                uint4 Ca = w2e[(j2 * 2 + 0) * 32];   // s2 = 0,1
                uint4 Cb = w2e[(j2 * 2 + 1) * 32];   // s2 = 2,3
                float4 wb = sWB2[(e * 4 + j2) * 4 + c];   // {w0,w1,b0,b1}
                #pragma unroll
                for (int r = 0; r < 2; r++) {
                    float a2[4] = {wb.z, wb.w, wb.z, wb.w};
                    mma16816(a2, ha[r][0], Ca.x, Ca.y);
                    mma16816(a2, ha[r][1], Ca.z, Ca.w);
                    mma16816(a2, ha[r][2], Cb.x, Cb.y);
                    mma16816(a2, ha[r][3], Cb.z, Cb.w);
                    p[r][0] += fmaxf(a2[0], 0.f) * wb.x + fmaxf(a2[1], 0.f) * wb.y;
                    p[r][1] += fmaxf(a2[2], 0.f) * wb.x + fmaxf(a2[3], 0.f) * wb.y;
                }
            }

            // ---- layer 3: quad reduce + sigmoid + prob-weighted accumulate ----
            #pragma unroll
            for (int r = 0; r < 2; r++) {
                p[r][0] += __shfl_xor_sync(0xffffffffu, p[r][0], 1);
                p[r][0] += __shfl_xor_sync(0xffffffffu, p[r][0], 2);
                p[r][1] += __shfl_xor_sync(0xffffffffu, p[r][1], 1);
                p[r][1] += __shfl_xor_sync(0xffffffffu, p[r][1], 2);
            }
            float b3e = sB3[e];
            if (c == 0) {
                #pragma unroll
                for (int r = 0; r < 2; r++) {
                    float z0 = p[r][0] + b3e;
                    float z1 = p[r][1] + b3e;
                    float s0 = 1.f / (1.f + __expf(-z0));
                    float s1 = 1.f / (1.f + __expf(-z1));
                    oa[r][0] += s0 * probs[(size_t)(rowbase + r * 16 + rq) * NUM_E + e];
                    oa[r][1] += s1 * probs[(size_t)(rowbase + r * 16 + 8 + rq) * NUM_E + e];
                }
            }
        }

        if (c == 0) {
            #pragma unroll
            for (int r = 0; r < 2; r++) {
                out[rowbase + r * 16 + rq]     = oa[r][0];
                out[rowbase + r * 16 + 8 + rq] = oa[r][1];
            }
        }
    }
}

extern "C" void kernel_launch(void* const* d_in, const int* in_sizes, int n_in,
                              void* d_out, int out_size) {
    const float* x     = (const float*)d_in[0];
    const float* probs = (const float*)d_in[1];
    const float* W1    = (const float*)d_in[2];
    const float* b1    = (const float*)d_in[3];
    const float* W2    = (const float*)d_in[4];
    const float* b2    = (const float*)d_in[5];
    const float* W3    = (const float*)d_in[6];
    const float* b3    = (const float*)d_in[7];
    float* out = (float*)d_out;

    const int B    = in_sizes[0] / 32;
    const int NT32 = B / 32;   // 16384 warp-tiles of 32 rows

    cudaFuncSetAttribute(moe_kernel, cudaFuncAttributeMaxDynamicSharedMemorySize, SMEM_BYTES);
    cudaFuncSetAttribute(moe_kernel, cudaFuncAttributePreferredSharedMemoryCarveout, 100);

    // 296 persistent CTAs (2 per SM), 2368 warps striding over 16384 tiles
    moe_kernel<<<296, 256, SMEM_BYTES>>>(x, probs, W1, b1, W2, b2, W3, b3, out, NT32);
}